// round 9
// baseline (speedup 1.0000x reference)
#include <cuda_runtime.h>
#include <math.h>
#include <stdint.h>

#define BB 8
#define SS 2048
#define DD 768

// Scratch (no cudaMalloc allowed): Q,K projections, transposed V, score matrix
__device__ float g_Q[BB * SS * DD];
__device__ float g_K[BB * SS * DD];
__device__ float g_Vt[BB * SS * DD];   // layout [e][b*s]  (ld = BB*SS)
__device__ float g_P[(long long)BB * SS * SS];

// 3-stage pipeline smem: [3][128][20] for A and B tiles
#define STAGE_F (128 * 20)
#define SMEM_BYTES (3 * 2 * STAGE_F * 4)

// cvt.rna.tf32.f32 requires a .b32 destination register
__device__ __forceinline__ float tf32r(float x) {
    uint32_t y;
    asm("cvt.rna.tf32.f32 %0, %1;" : "=r"(y) : "f"(x));
    return __uint_as_float(y);
}
__device__ __forceinline__ uint32_t tf32u(uint32_t x) {
    uint32_t y;
    asm("cvt.rna.tf32.f32 %0, %1;" : "=r"(y) : "f"(__uint_as_float(x)));
    return y;
}

__device__ __forceinline__ void mma_tf32(float c[4],
                                         uint32_t a0, uint32_t a1, uint32_t a2, uint32_t a3,
                                         uint32_t b0, uint32_t b1) {
    asm volatile(
        "mma.sync.aligned.m16n8k8.row.col.f32.tf32.tf32.f32 "
        "{%0,%1,%2,%3}, {%4,%5,%6,%7}, {%8,%9}, {%0,%1,%2,%3};\n"
        : "+f"(c[0]), "+f"(c[1]), "+f"(c[2]), "+f"(c[3])
        : "r"(a0), "r"(a1), "r"(a2), "r"(a3), "r"(b0), "r"(b1));
}

// ldmatrix x4 of 8x8 b16 matrices == four 8x4 tf32 blocks; thread t receives
// tf32 element (t/4, t%4) of each matrix -> exact tf32 mma fragment layout.
__device__ __forceinline__ void ldsm4(uint32_t& r0, uint32_t& r1, uint32_t& r2, uint32_t& r3,
                                      uint32_t addr) {
    asm volatile("ldmatrix.sync.aligned.m8n8.x4.shared.b16 {%0,%1,%2,%3}, [%4];\n"
                 : "=r"(r0), "=r"(r1), "=r"(r2), "=r"(r3) : "r"(addr));
}

__device__ __forceinline__ void cpasync16(uint32_t dst, const void* src) {
    asm volatile("cp.async.cg.shared.global [%0], [%1], 16;\n" :: "r"(dst), "l"(src));
}

// ---------------------------------------------------------------------------
// tf32 tensor-core NT GEMM: C = scale*(A @ B^T) + bias
//   A:[M,K] ld=lda, B:[N,K] ld=ldb (both K-contiguous), C:[M,N] ld=ldc.
// 128x128 block tile, Kc=16, 3-stage cp.async pipeline (ONE barrier/iter),
// 256 threads (8 warps), warp tile 32(M)x64(N) = 2x8 m16n8k8 mma tiles,
// fragments via ldmatrix.x4.b16.
// CVT: round operands to tf32 at consume. RND: round outputs to tf32.
// BROW: bias indexed by M-row (transposed-V projection) else by N-col.
// Smem [128][20]: ldmatrix rows at 80B stride -> all banks once, conflict-free.
// ---------------------------------------------------------------------------
template <bool CVT, bool RND, bool BROW>
__global__ void __launch_bounds__(256, 2)
gemm_nt(const float* __restrict__ A, const float* __restrict__ Bm,
        const float* __restrict__ bias, float* __restrict__ C,
        int K, int lda, int ldb, int ldc,
        long long sA, long long sB, long long sC, float scale)
{
    extern __shared__ __align__(16) float smem[];

    const int b = blockIdx.z;
    A  += (long long)b * sA;
    Bm += (long long)b * sB;
    C  += (long long)b * sC;

    const int tid   = threadIdx.x;
    const int lane  = tid & 31;
    const int warp  = tid >> 5;
    const int warpM = warp & 3;       // 0..3 -> 32-row slab
    const int warpN = warp >> 2;      // 0..1 -> 64-col slab
    const int grp   = lane >> 2;      // 0..7
    const int qid   = lane & 3;       // 0..3
    const int m0    = blockIdx.y * 128;
    const int n0    = blockIdx.x * 128;

    // ldmatrix per-thread row assignment: local row + matrix select
    const int local = lane & 7;
    const int sel   = lane >> 3;      // 0..3
    // A: matrices ordered (row-lo,k-lo),(row-hi,k-lo),(row-lo,k-hi),(row-hi,k-hi)
    const int rowA = warpM * 32 + ((sel & 1) << 3) + local;
    const int kcA  = (sel >> 1) << 2;
    // B: matrices ordered (n-lo,k-lo),(n-lo,k-hi),(n-hi,k-lo),(n-hi,k-hi)
    const int rowB = warpN * 64 + ((sel >> 1) << 3) + local;
    const int kcB  = (sel & 1) << 2;

    const uint32_t as_base = (uint32_t)__cvta_generic_to_shared(smem);
    const uint32_t STAGE   = STAGE_F * 4;            // bytes per tile stage
    const uint32_t bs_base = as_base + 3 * STAGE;

    float acc[2][8][4];
#pragma unroll
    for (int mt = 0; mt < 2; mt++)
#pragma unroll
        for (int nt = 0; nt < 8; nt++)
#pragma unroll
            for (int r = 0; r < 4; r++) acc[mt][nt][r] = 0.f;

    // ---- async stage loader: A 128x16, B 128x16 (both K-contiguous)
    auto load_stage = [&](int k0, int s) {
#pragma unroll
        for (int i = 0; i < 2; i++) {
            int slot = tid + i * 256;            // 0..511
            int row  = slot >> 2;                // 0..127
            int c4   = (slot & 3) << 2;          // 0,4,8,12
            cpasync16(as_base + s * STAGE + (row * 20 + c4) * 4,
                      &A[(long long)(m0 + row) * lda + k0 + c4]);
            cpasync16(bs_base + s * STAGE + (row * 20 + c4) * 4,
                      &Bm[(long long)(n0 + row) * ldb + k0 + c4]);
        }
        asm volatile("cp.async.commit_group;\n" ::);
    };

    const int NK = K >> 4;
    load_stage(0, 0);
    load_stage(16, 1);

    int s = 0;           // stage of current iteration
    int sl = 2;          // stage the next prefetch writes
    for (int it = 0; it < NK; it++) {
        // Stage `it` must be complete. Pending groups here: {it, it+1} (or {it}
        // at the final iteration) -> wait until <=1 (resp. 0) remain.
        if (it < NK - 1) asm volatile("cp.async.wait_group 1;\n" ::);
        else             asm volatile("cp.async.wait_group 0;\n" ::);
        // One barrier: publishes stage `it` to all warps AND proves all warps
        // finished stage `it-1` == buffer sl (reuse distance 3) -> safe to load.
        __syncthreads();
        if (it + 2 < NK) load_stage((it + 2) << 4, sl);

        const uint32_t as_s = as_base + s * STAGE;
        const uint32_t bs_s = bs_base + s * STAGE;

#pragma unroll
        for (int ks = 0; ks < 2; ks++) {
            const int kb = ks * 8;
            uint32_t af[2][4];
#pragma unroll
            for (int mt = 0; mt < 2; mt++) {
                uint32_t addr = as_s + (((rowA + mt * 16) * 20) + kb + kcA) * 4;
                ldsm4(af[mt][0], af[mt][1], af[mt][2], af[mt][3], addr);
                if (CVT) {
                    af[mt][0] = tf32u(af[mt][0]); af[mt][1] = tf32u(af[mt][1]);
                    af[mt][2] = tf32u(af[mt][2]); af[mt][3] = tf32u(af[mt][3]);
                }
            }
#pragma unroll
            for (int p = 0; p < 4; p++) {       // nt pair p -> nt=2p, 2p+1
                uint32_t b0, b1, b2, b3;
                uint32_t addr = bs_s + (((rowB + p * 16) * 20) + kb + kcB) * 4;
                ldsm4(b0, b1, b2, b3, addr);
                if (CVT) { b0 = tf32u(b0); b1 = tf32u(b1); b2 = tf32u(b2); b3 = tf32u(b3); }
#pragma unroll
                for (int mt = 0; mt < 2; mt++) {
                    mma_tf32(acc[mt][2 * p],     af[mt][0], af[mt][1], af[mt][2], af[mt][3], b0, b1);
                    mma_tf32(acc[mt][2 * p + 1], af[mt][0], af[mt][1], af[mt][2], af[mt][3], b2, b3);
                }
            }
        }

        s  = (s  == 2) ? 0 : s  + 1;
        sl = (sl == 2) ? 0 : sl + 1;
    }

    // ---- epilogue: scale + bias (+ optional tf32 rounding), float2 stores
#pragma unroll
    for (int nt = 0; nt < 8; nt++) {
        int colc = n0 + warpN * 64 + nt * 8 + (qid << 1);
        float bc0 = 0.f, bc1 = 0.f;
        if (bias && !BROW) { bc0 = bias[colc]; bc1 = bias[colc + 1]; }
#pragma unroll
        for (int mt = 0; mt < 2; mt++) {
            int row0 = m0 + warpM * 32 + mt * 16 + grp;
            float br0 = 0.f, br1 = 0.f;
            if (bias && BROW) { br0 = bias[row0]; br1 = bias[row0 + 8]; }
            float2 o0, o1;
            o0.x = acc[mt][nt][0] * scale + (BROW ? br0 : bc0);
            o0.y = acc[mt][nt][1] * scale + (BROW ? br0 : bc1);
            o1.x = acc[mt][nt][2] * scale + (BROW ? br1 : bc0);
            o1.y = acc[mt][nt][3] * scale + (BROW ? br1 : bc1);
            if (RND) {
                o0.x = tf32r(o0.x); o0.y = tf32r(o0.y);
                o1.x = tf32r(o1.x); o1.y = tf32r(o1.y);
            }
            *(float2*)&C[(long long)row0 * ldc + colc]       = o0;
            *(float2*)&C[(long long)(row0 + 8) * ldc + colc] = o1;
        }
    }
}

// ---------------------------------------------------------------------------
// Row softmax over P rows of length SS (2048). One block (256 thr) per row.
// Output rounded to tf32 so the PV GEMM can skip per-element cvt.
// ---------------------------------------------------------------------------
__global__ void __launch_bounds__(256)
softmax_rows(float* __restrict__ P)
{
    float* p = P + (long long)blockIdx.x * SS;
    const int tid  = threadIdx.x;
    const int lane = tid & 31;
    const int wid  = tid >> 5;

    __shared__ float red[8];

    float v[8];
    float mx = -1e30f;
#pragma unroll
    for (int i = 0; i < 8; i++) {
        v[i] = p[tid + i * 256];
        mx = fmaxf(mx, v[i]);
    }
#pragma unroll
    for (int o = 16; o > 0; o >>= 1)
        mx = fmaxf(mx, __shfl_xor_sync(0xffffffffu, mx, o));
    if (lane == 0) red[wid] = mx;
    __syncthreads();
    float rmax = red[0];
#pragma unroll
    for (int i = 1; i < 8; i++) rmax = fmaxf(rmax, red[i]);
    __syncthreads();

    float s = 0.f;
#pragma unroll
    for (int i = 0; i < 8; i++) {
        v[i] = __expf(v[i] - rmax);
        s += v[i];
    }
#pragma unroll
    for (int o = 16; o > 0; o >>= 1)
        s += __shfl_xor_sync(0xffffffffu, s, o);
    if (lane == 0) red[wid] = s;
    __syncthreads();
    float tot = 0.f;
#pragma unroll
    for (int i = 0; i < 8; i++) tot += red[i];
    float inv = 1.f / tot;

#pragma unroll
    for (int i = 0; i < 8; i++)
        p[tid + i * 256] = tf32r(v[i] * inv);
}

// ---------------------------------------------------------------------------
// Launch: Q,K projections + transposed V projection -> scores -> softmax -> PV
// ---------------------------------------------------------------------------
extern "C" void kernel_launch(void* const* d_in, const int* in_sizes, int n_in,
                              void* d_out, int out_size)
{
    const float* Z  = (const float*)d_in[0];
    const float* Wq = (const float*)d_in[1];
    const float* bq = (const float*)d_in[2];
    const float* Wk = (const float*)d_in[3];
    const float* bk = (const float*)d_in[4];
    const float* Wv = (const float*)d_in[5];
    const float* bv = (const float*)d_in[6];
    float* out = (float*)d_out;

    float *Qp, *Kp, *Vtp, *Pp;
    cudaGetSymbolAddress((void**)&Qp,  g_Q);
    cudaGetSymbolAddress((void**)&Kp,  g_K);
    cudaGetSymbolAddress((void**)&Vtp, g_Vt);
    cudaGetSymbolAddress((void**)&Pp,  g_P);

    // Opt in to >48KB dynamic smem (idempotent, capture-safe host calls)
    cudaFuncSetAttribute(gemm_nt<true,  true,  false>,
                         cudaFuncAttributeMaxDynamicSharedMemorySize, SMEM_BYTES);
    cudaFuncSetAttribute(gemm_nt<true,  true,  true>,
                         cudaFuncAttributeMaxDynamicSharedMemorySize, SMEM_BYTES);
    cudaFuncSetAttribute(gemm_nt<false, false, false>,
                         cudaFuncAttributeMaxDynamicSharedMemorySize, SMEM_BYTES);

    dim3 blk(256);
    const long long SD  = (long long)SS * DD;
    const long long SSs = (long long)SS * SS;
    const int BS = BB * SS;
    const float scale = 1.0f / sqrtf((float)DD);

    // Q,K projections: [B*S, D] x [D, D]^T  (M=16384, N=768, K=768)
    dim3 gq(DD / 128, BS / 128, 1);
    gemm_nt<true, true, false><<<gq, blk, SMEM_BYTES>>>(Z, Wq, bq, Qp, DD, DD, DD, DD, 0, 0, 0, 1.0f);
    gemm_nt<true, true, false><<<gq, blk, SMEM_BYTES>>>(Z, Wk, bk, Kp, DD, DD, DD, DD, 0, 0, 0, 1.0f);

    // Transposed V projection: Vt = Wv @ Z^T  (M=768, N=16384, K=768),
    // bias applied per M-row; output layout Vt[e][b*s], ld = B*S.
    dim3 gv(BS / 128, DD / 128, 1);
    gemm_nt<true, true, true ><<<gv, blk, SMEM_BYTES>>>(Wv, Z, bv, Vtp, DD, DD, DD, BS, 0, 0, 0, 1.0f);

    // Scores: per batch, Q @ K^T * scale (operands pre-rounded): M=N=2048, K=768
    dim3 gs(SS / 128, SS / 128, BB);
    gemm_nt<false, false, false><<<gs, blk, SMEM_BYTES>>>(Qp, Kp, nullptr, Pp, DD, DD, DD, SS, SD, SD, SSs, scale);

    // Softmax over each of B*S rows (rounds P to tf32 on store)
    softmax_rows<<<BS, blk>>>(Pp);

    // Output: per batch, P @ Vt^T (NT): M=2048, N=768, K=2048
    // B = Vt[e][b*s]: ldb = B*S, batch stride = SS.
    dim3 go(DD / 128, SS / 128, BB);
    gemm_nt<false, false, false><<<go, blk, SMEM_BYTES>>>(Pp, Vtp, nullptr, out, SS, SS, BS, DD, SSs, SS, SD, 1.0f);
}